// round 13
// baseline (speedup 1.0000x reference)
#include <cuda_runtime.h>
#include <cuda_bf16.h>
#include <cstdint>
#include <cstddef>
#include <math.h>

// Problem constants
#define BATCH 768
#define UNITS 256
#define DHID  1024
#define GROUPS 8
#define J1N   96              // BATCH / GROUPS
#define BATCH2 1536           // 2 * BATCH (key rows then query rows)
#define W_ELEMS 150994944ll   // 768*768*256

// ---------------- device scratch (no allocations allowed) ----------------
__device__ float g_H[BATCH2 * DHID];          // hidden activations (leaky), 6.3MB
__device__ float g_part[4 * BATCH2 * UNITS];  // split-K partials for GEMM2
__device__ float g_Ek [BATCH * UNITS];        // exp(key*t)
__device__ float g_iEk[BATCH * UNITS];        // 1/exp(key*t)
__device__ float g_Eq [BATCH * UNITS];        // exp(query*t)
__device__ float g_iEq[BATCH * UNITS];        // 1/exp(query*t)
__device__ int   g_mask_mode;                 // 0=f32, 1=bf16, 2=i32, 3=u8
__device__ int   g_cnt[96];                   // split-K arrival counters (self-reset)

__device__ __forceinline__ bool mask_at(const void* m, int mode, int idx) {
    switch (mode) {
        case 0:  return ((const float*)m)[idx] != 0.0f;
        case 1:  return ((const unsigned short*)m)[idx] != 0;
        case 2:  return ((const int*)m)[idx] != 0;
        default: return ((const unsigned char*)m)[idx] != 0;
    }
}

// ---------------- standalone mask dtype detection (tail path only) -------
__global__ void k_detect_mask(const unsigned char* __restrict__ m) {
    __shared__ int ok[4];
    if (threadIdx.x < 4) ok[threadIdx.x] = 1;
    __syncthreads();
    const unsigned int* w = (const unsigned int*)m;
    for (int idx = threadIdx.x; idx < 256; idx += blockDim.x) {
        unsigned int v = w[idx];
        if (!(v == 0u || v == 0x3F800000u)) atomicAnd(&ok[0], 0);
        unsigned int h0 = v & 0xFFFFu, h1 = v >> 16;
        if (!((h0 == 0u || h0 == 0x3F80u) && (h1 == 0u || h1 == 0x3F80u)))
            atomicAnd(&ok[1], 0);
        if (v > 1u) atomicAnd(&ok[2], 0);
        if ((v & 0xFEFEFEFEu) != 0u) atomicAnd(&ok[3], 0);
    }
    __syncthreads();
    if (threadIdx.x == 0)
        g_mask_mode = ok[0] ? 0 : (ok[1] ? 1 : (ok[2] ? 2 : 3));
}

// ---------------- GEMM1: H[1536,1024] = leaky(X2[1536,256] @ W1 + b1) ----
// Double-buffered smem pipeline; inner FMA loop identical to the measured-
// good R2 version. X2 rows 0..767 = x, rows 768..1535 = masked x.
#define BM 64
#define BN 64
#define BK 16

__global__ __launch_bounds__(256) void k_gemm1(
    const float* __restrict__ x, const void* __restrict__ mask,
    const float* __restrict__ W1, const float* __restrict__ b1)
{
    __shared__ float As[2][BK][BM];
    __shared__ float Bs[2][BK][BN];
    const int tid = threadIdx.x;

    // inline mask dtype detection (uniform result, cheap barriers)
    {
        unsigned int v = ((const unsigned int*)mask)[tid];
        unsigned int h0 = v & 0xFFFFu, h1 = v >> 16;
        int m_f32 = __syncthreads_and((v == 0u) || (v == 0x3F800000u));
        int m_bf  = __syncthreads_and((h0 == 0u || h0 == 0x3F80u) &&
                                      (h1 == 0u || h1 == 0x3F80u));
        int m_i32 = __syncthreads_and(v <= 1u);
        g_mask_mode = m_f32 ? 0 : (m_bf ? 1 : (m_i32 ? 2 : 3));
    }
    const int mmode = g_mask_mode;

    const int bn = blockIdx.x;            // 0..15
    const int bm = blockIdx.y;            // 0..23
    const int tx = tid & 15, ty = tid >> 4;
    const int row0 = bm * BM, col0 = bn * BN;

    const int am  = tid >> 2;             // 0..63 (row in tile)
    const int akq = (tid & 3) * 4;        // 0,4,8,12 (k quad)
    const int bk_ = tid >> 4;             // 0..15 (k in tile)
    const int bnq = (tid & 15) * 4;       // n quad

    const int gr = row0 + am;
    const bool isq = (gr >= BATCH);
    const int xrow = isq ? (gr - BATCH) : gr;

    float acc[4][4];
#pragma unroll
    for (int r = 0; r < 4; r++)
#pragma unroll
        for (int c = 0; c < 4; c++) acc[r][c] = 0.f;

    // load tile for step s into registers
    auto loadA = [&](int s, float4& av) {
        int base = xrow * UNITS + s * BK + akq;
        av = *(const float4*)(x + base);
        if (isq) {
            if (mask_at(mask, mmode, base + 0)) av.x = 0.f;
            if (mask_at(mask, mmode, base + 1)) av.y = 0.f;
            if (mask_at(mask, mmode, base + 2)) av.z = 0.f;
            if (mask_at(mask, mmode, base + 3)) av.w = 0.f;
        }
    };

    // preload step 0
    {
        float4 av; loadA(0, av);
        As[0][akq + 0][am] = av.x; As[0][akq + 1][am] = av.y;
        As[0][akq + 2][am] = av.z; As[0][akq + 3][am] = av.w;
        *(float4*)&Bs[0][bk_][bnq] =
            *(const float4*)(W1 + (size_t)(0 + bk_) * DHID + col0 + bnq);
        __syncthreads();
    }

    const int NSTEP = UNITS / BK;         // 16
    for (int s = 0; s < NSTEP; s++) {
        const int cur = s & 1;
        float4 av2, bv2;
        const bool more = (s + 1 < NSTEP);
        if (more) {
            loadA(s + 1, av2);
            bv2 = *(const float4*)(W1 + (size_t)((s + 1) * BK + bk_) * DHID
                                   + col0 + bnq);
        }
#pragma unroll
        for (int kk = 0; kk < BK; kk++) {
            float4 a4 = *(const float4*)&As[cur][kk][ty * 4];
            float4 b4 = *(const float4*)&Bs[cur][kk][tx * 4];
            float a[4] = {a4.x, a4.y, a4.z, a4.w};
            float b[4] = {b4.x, b4.y, b4.z, b4.w};
#pragma unroll
            for (int r = 0; r < 4; r++)
#pragma unroll
                for (int c = 0; c < 4; c++) acc[r][c] += a[r] * b[c];
        }
        if (more) {
            const int nxt = cur ^ 1;
            As[nxt][akq + 0][am] = av2.x; As[nxt][akq + 1][am] = av2.y;
            As[nxt][akq + 2][am] = av2.z; As[nxt][akq + 3][am] = av2.w;
            *(float4*)&Bs[nxt][bk_][bnq] = bv2;
        }
        __syncthreads();
    }

    float4 bb = *(const float4*)(b1 + col0 + tx * 4);
    float bias[4] = {bb.x, bb.y, bb.z, bb.w};
#pragma unroll
    for (int r = 0; r < 4; r++) {
        int gm = row0 + ty * 4 + r;
        float4 o;
        float v0 = acc[r][0] + bias[0]; o.x = v0 > 0.f ? v0 : 0.01f * v0;
        float v1 = acc[r][1] + bias[1]; o.y = v1 > 0.f ? v1 : 0.01f * v1;
        float v2 = acc[r][2] + bias[2]; o.z = v2 > 0.f ? v2 : 0.01f * v2;
        float v3 = acc[r][3] + bias[3]; o.w = v3 > 0.f ? v3 : 0.01f * v3;
        *(float4*)(g_H + (size_t)gm * DHID + col0 + tx * 4) = o;
    }
}

// ---------------- GEMM2 (split-K=4) + fused reduce/exp fixup -------------
// part[kz] = H[:, kz*256:(kz+1)*256] @ W2-slice.  The LAST arriving block
// per output tile sums the 4 partials, adds b2, scales by temperature and
// writes the exp tables.  Counters self-reset -> graph-replay safe.
__global__ __launch_bounds__(256) void k_gemm2(
    const float* __restrict__ W2, const float* __restrict__ b2,
    const float* __restrict__ temp)
{
    __shared__ float As[2][BK][BM];
    __shared__ float Bs[2][BK][BN];
    __shared__ int s_old;
    const int bn = blockIdx.x;            // 0..3
    const int bm = blockIdx.y;            // 0..23
    const int kz = blockIdx.z;            // 0..3
    const int tid = threadIdx.x;
    const int tx = tid & 15, ty = tid >> 4;
    const int row0 = bm * BM, col0 = bn * BN;
    const int kbeg = kz * 256;

    const int am  = tid >> 2;
    const int akq = (tid & 3) * 4;
    const int bk_ = tid >> 4;
    const int bnq = (tid & 15) * 4;
    const int gr = row0 + am;

    float acc[4][4];
#pragma unroll
    for (int r = 0; r < 4; r++)
#pragma unroll
        for (int c = 0; c < 4; c++) acc[r][c] = 0.f;

    // preload step 0
    {
        float4 av = *(const float4*)(g_H + (size_t)gr * DHID + kbeg + akq);
        As[0][akq + 0][am] = av.x; As[0][akq + 1][am] = av.y;
        As[0][akq + 2][am] = av.z; As[0][akq + 3][am] = av.w;
        *(float4*)&Bs[0][bk_][bnq] =
            *(const float4*)(W2 + (size_t)(kbeg + bk_) * UNITS + col0 + bnq);
        __syncthreads();
    }

    const int NSTEP = 256 / BK;           // 16
    for (int s = 0; s < NSTEP; s++) {
        const int cur = s & 1;
        float4 av2, bv2;
        const bool more = (s + 1 < NSTEP);
        if (more) {
            int k0 = kbeg + (s + 1) * BK;
            av2 = *(const float4*)(g_H + (size_t)gr * DHID + k0 + akq);
            bv2 = *(const float4*)(W2 + (size_t)(k0 + bk_) * UNITS + col0 + bnq);
        }
#pragma unroll
        for (int kk = 0; kk < BK; kk++) {
            float4 a4 = *(const float4*)&As[cur][kk][ty * 4];
            float4 b4 = *(const float4*)&Bs[cur][kk][tx * 4];
            float a[4] = {a4.x, a4.y, a4.z, a4.w};
            float b[4] = {b4.x, b4.y, b4.z, b4.w};
#pragma unroll
            for (int r = 0; r < 4; r++)
#pragma unroll
                for (int c = 0; c < 4; c++) acc[r][c] += a[r] * b[c];
        }
        if (more) {
            const int nxt = cur ^ 1;
            As[nxt][akq + 0][am] = av2.x; As[nxt][akq + 1][am] = av2.y;
            As[nxt][akq + 2][am] = av2.z; As[nxt][akq + 3][am] = av2.w;
            *(float4*)&Bs[nxt][bk_][bnq] = bv2;
        }
        __syncthreads();
    }

    // store this kz's partial
    float* outp = g_part + (size_t)kz * BATCH2 * UNITS;
#pragma unroll
    for (int r = 0; r < 4; r++) {
        int gm = row0 + ty * 4 + r;
        float4 o = make_float4(acc[r][0], acc[r][1], acc[r][2], acc[r][3]);
        *(float4*)(outp + (size_t)gm * UNITS + col0 + tx * 4) = o;
    }

    // split-K fixup: last arriver reduces + builds exp tables for this tile
    const int tile = bm * 4 + bn;
    __threadfence();
    if (tid == 0) s_old = atomicAdd(&g_cnt[tile], 1);
    __syncthreads();
    if (s_old == 3) {
        __threadfence();                  // acquire partials from peer blocks
        const int S = BATCH2 * UNITS;
        const bool iskey = (row0 < BATCH);  // tiles never straddle (768 = 12*64)
#pragma unroll
        for (int e = tid; e < (BM * BN) / 4; e += 256) {
            int r  = e >> 4;              // row in tile 0..63
            int c4 = (e & 15) * 4;        // col quad
            int row = row0 + r;
            int u   = col0 + c4;
            int idx = row * UNITS + u;
            float4 p0 = *(const float4*)(g_part + idx);
            float4 p1 = *(const float4*)(g_part + idx + S);
            float4 p2 = *(const float4*)(g_part + idx + 2 * S);
            float4 p3 = *(const float4*)(g_part + idx + 3 * S);
            float4 bb = *(const float4*)(b2 + u);
            float4 tt = *(const float4*)(temp + u);
            float4 ev, iv;
            ev.x = expf((p0.x + p1.x + p2.x + p3.x + bb.x) * tt.x); iv.x = 1.0f / ev.x;
            ev.y = expf((p0.y + p1.y + p2.y + p3.y + bb.y) * tt.y); iv.y = 1.0f / ev.y;
            ev.z = expf((p0.z + p1.z + p2.z + p3.z + bb.z) * tt.z); iv.z = 1.0f / ev.z;
            ev.w = expf((p0.w + p1.w + p2.w + p3.w + bb.w) * tt.w); iv.w = 1.0f / ev.w;
            if (iskey) {
                *(float4*)(g_Ek  + idx) = ev;
                *(float4*)(g_iEk + idx) = iv;
            } else {
                int o = idx - BATCH * UNITS;
                *(float4*)(g_Eq  + o) = ev;
                *(float4*)(g_iEq + o) = iv;
            }
        }
        if (tid == 0) g_cnt[tile] = 0;    // reset for next graph replay
    }
}

// ---------------- fused softmax + write (the 604MB kernel) ----------------
// At the HBM write wall (~5 TB/s measured across layouts) — do not touch.
// exp(-|k-q|t) = min(Ek*invEq, Eq*invEk).  Block owns ONE j2 and ALL 256 u;
// thread keeps Ek/invEk for its (j2,u) over all 96 j1 in registers.
#define NBI 37
__global__ __launch_bounds__(256, 1) void k_softmax_write(float* __restrict__ w)
{
    const int j2 = blockIdx.x;                 // 0..7
    const int ib = blockIdx.y;                 // 0..NBI-1
    const int lane = threadIdx.x & 31;
    const int uc = threadIdx.x >> 5;           // 0..7 (u chunk)
    const int u = uc * 32 + lane;

    float ek[J1N], iek[J1N];
    const float* Ekp  = g_Ek  + j2 * UNITS + u;
    const float* iEkp = g_iEk + j2 * UNITS + u;
#pragma unroll
    for (int j1 = 0; j1 < J1N; j1++) {
        ek[j1]  = Ekp [j1 * (GROUPS * UNITS)];
        iek[j1] = iEkp[j1 * (GROUPS * UNITS)];
    }

    const int i0 = (ib * BATCH) / NBI;
    const int i1 = ((ib + 1) * BATCH) / NBI;
    for (int i = i0; i < i1; i++) {
        float eq  = g_Eq [i * UNITS + u];
        float ieq = g_iEq[i * UNITS + u];
        float s = 0.f;
#pragma unroll
        for (int j1 = 0; j1 < J1N; j1++)
            s += fminf(ek[j1] * ieq, iek[j1] * eq);
        const bool diag = ((i & 7) == j2);     // uniform across block
        const int jd = i >> 3;
        if (diag) s -= fminf(ek[jd] * ieq, iek[jd] * eq);
        float r = 1.0f / (8.0f * s);
        float f1 = ieq * r, f2 = eq * r;
        float* base = w + ((size_t)i * BATCH + j2) * UNITS + u;
#pragma unroll
        for (int j1 = 0; j1 < J1N; j1++)
            __stcs(base + (size_t)j1 * (GROUPS * UNITS),
                   fminf(ek[j1] * f1, iek[j1] * f2));
        if (diag) __stcs(base + (size_t)jd * (GROUPS * UNITS), 0.0f);
    }
}

// ---------------- optional mask tail of the tuple output -----------------
__global__ void k_mask_tail(float* __restrict__ out, const void* __restrict__ mask,
                            long long extra)
{
    long long idx = (long long)blockIdx.x * blockDim.x + threadIdx.x;
    if (idx >= extra) return;
    float v = 0.0f;
    if (idx < BATCH * UNITS)
        v = mask_at(mask, g_mask_mode, (int)idx) ? 1.0f : 0.0f;
    out[idx] = v;
}

// ---------------- launch ----------------
extern "C" void kernel_launch(void* const* d_in, const int* in_sizes, int n_in,
                              void* d_out, int out_size)
{
    const float* x    = (const float*)d_in[0];
    const void*  mask = d_in[1];
    const float* W1   = (const float*)d_in[2];
    const float* b1   = (const float*)d_in[3];
    const float* W2   = (const float*)d_in[4];
    const float* b2   = (const float*)d_in[5];
    const float* temp = (const float*)d_in[6];
    float* out = (float*)d_out;

    // H = leaky(X2 @ W1 + b1)   (mask-mode detection inlined)
    k_gemm1<<<dim3(DHID / BN, BATCH2 / BM), 256>>>(x, mask, W1, b1);

    // partials = H @ W2 (split-K) + fused reduce/exp fixup
    k_gemm2<<<dim3(UNITS / BN, BATCH2 / BM, 4), 256>>>(W2, b2, temp);

    // big fused softmax + write: grid = 8 j2 x NBI i-blocks
    k_softmax_write<<<dim3(GROUPS, NBI), 256>>>(out);

    // if output is the whole tuple (w, mask), fill the mask tail
    long long extra = (long long)out_size - W_ELEMS;
    if (extra > 0) {
        k_detect_mask<<<1, 256>>>((const unsigned char*)mask);
        int nb = (int)((extra + 255) / 256);
        k_mask_tail<<<nb, 256>>>(out + W_ELEMS, mask, extra);
    }
}